// round 9
// baseline (speedup 1.0000x reference)
#include <cuda_runtime.h>
#include <cuda_bf16.h>

// 3x3 median blur, zero padding, 48 planes of 512x512 fp32.
// R9: identical math and layout to R8 (17.5 exact min/max ops per output,
// 4-wide x 4-tall per thread, 256-thr blocks). Single change:
// __launch_bounds__(256, 6) caps regs at ~42 so 6 blocks fit per SM
// (48 warps, 75% occ ceiling vs 62.5% at 48 regs). The kernel is
// latency-bound (issue 49%, no pipe >59%), so occupancy is the lever.

constexpr int W = 512;
constexpr int H = 512;

__device__ __forceinline__ float med3f(float a, float b, float c) {
    return fmaxf(fminf(a, b), fminf(fmaxf(a, b), c));
}

// Load 6 columns [x0-1 .. x0+4] of row yy into c (zeros outside the plane).
__device__ __forceinline__ void load6(float c[6], const float* __restrict__ pb,
                                      int yy, int x0) {
    if (yy < 0 || yy >= H) {
        #pragma unroll
        for (int i = 0; i < 6; i++) c[i] = 0.0f;
        return;
    }
    const float* row = pb + (size_t)yy * W;
    const float4 v = *reinterpret_cast<const float4*>(row + x0);
    c[1] = v.x; c[2] = v.y; c[3] = v.z; c[4] = v.w;
    c[0] = (x0 > 0)     ? __ldg(row + x0 - 1) : 0.0f;
    c[5] = (x0 + 4 < W) ? __ldg(row + x0 + 4) : 0.0f;
}

// One output row: insert row r into the sorted pair (a<=b), then merge the
// 4 overlapping column-triples with shared pairwise extremes.
__device__ __forceinline__ void window_ins_store(
    const float a[6], const float b[6], const float r[6],
    float* __restrict__ q)
{
    float lo[6], mi[6], hi[6];
    #pragma unroll
    for (int i = 0; i < 6; i++) {
        const float mbr = fminf(b[i], r[i]);
        lo[i] = fminf(a[i], r[i]);
        mi[i] = fmaxf(a[i], mbr);
        hi[i] = fmaxf(b[i], r[i]);
    }

    // max-of-los with shared interior pairs
    const float pmx1 = fmaxf(lo[1], lo[2]);
    const float pmx3 = fmaxf(lo[3], lo[4]);
    const float mx0 = fmaxf(lo[0], pmx1);
    const float mx1 = fmaxf(pmx1, lo[3]);
    const float mx2 = fmaxf(lo[2], pmx3);
    const float mx3 = fmaxf(pmx3, lo[5]);

    // min-of-his with shared interior pairs
    const float pmn1 = fminf(hi[1], hi[2]);
    const float pmn3 = fminf(hi[3], hi[4]);
    const float mn0 = fminf(hi[0], pmn1);
    const float mn1 = fminf(pmn1, hi[3]);
    const float mn2 = fminf(hi[2], pmn3);
    const float mn3 = fminf(pmn3, hi[5]);

    // med-of-mids: clamp the third element into a shared sorted pair
    const float s12 = fminf(mi[1], mi[2]);
    const float t12 = fmaxf(mi[1], mi[2]);
    const float s34 = fminf(mi[3], mi[4]);
    const float t34 = fmaxf(mi[3], mi[4]);
    const float md0 = fmaxf(s12, fminf(t12, mi[0]));
    const float md1 = fmaxf(s12, fminf(t12, mi[3]));
    const float md2 = fmaxf(s34, fminf(t34, mi[2]));
    const float md3 = fmaxf(s34, fminf(t34, mi[5]));

    float4 o;
    o.x = med3f(mx0, md0, mn0);
    o.y = med3f(mx1, md1, mn1);
    o.z = med3f(mx2, md2, mn2);
    o.w = med3f(mx3, md3, mn3);
    *reinterpret_cast<float4*>(q) = o;
}

__global__ void __launch_bounds__(256, 6) median3x3_kernel(
    const float* __restrict__ in, float* __restrict__ out)
{
    const int plane = blockIdx.y;                               // 0..47
    const int x0    = threadIdx.x * 4;                          // 0..508
    const int y0    = (blockIdx.x * 2 + threadIdx.y) * 4;       // top output row

    const float* pbase = in  + (size_t)plane * (H * W);
    float*       qb    = out + (size_t)plane * (H * W) + (size_t)y0 * W + x0;

    float rm1[6], r0[6], r1[6], r2[6], r3[6], r4[6];
    float pa[6], pb2[6];

    // Rows for windows 0 and 1 (batched for MLP).
    load6(rm1, pbase, y0 - 1, x0);
    load6(r0,  pbase, y0,     x0);
    load6(r1,  pbase, y0 + 1, x0);
    load6(r2,  pbase, y0 + 2, x0);

    // Shared sorted pair of rows (y0, y0+1).
    #pragma unroll
    for (int i = 0; i < 6; i++) {
        pa[i]  = fminf(r0[i], r1[i]);
        pb2[i] = fmaxf(r0[i], r1[i]);
    }
    window_ins_store(pa, pb2, rm1, qb);              // rows y0-1..y0+1
    window_ins_store(pa, pb2, r2,  qb + W);          // rows y0..y0+2

    // Rows for windows 2 and 3.
    load6(r3, pbase, y0 + 3, x0);
    load6(r4, pbase, y0 + 4, x0);

    // Shared sorted pair of rows (y0+2, y0+3).
    #pragma unroll
    for (int i = 0; i < 6; i++) {
        pa[i]  = fminf(r2[i], r3[i]);
        pb2[i] = fmaxf(r2[i], r3[i]);
    }
    window_ins_store(pa, pb2, r1, qb + 2 * W);       // rows y0+1..y0+3
    window_ins_store(pa, pb2, r4, qb + 3 * W);       // rows y0+2..y0+4
}

extern "C" void kernel_launch(void* const* d_in, const int* in_sizes, int n_in,
                              void* d_out, int out_size)
{
    const float* in  = (const float*)d_in[0];
    float*       out = (float*)d_out;

    // Block: 128 x-groups (4 px) x 2 tile-rows (256 thr); 4 rows per thread.
    dim3 block(128, 2, 1);
    dim3 grid(512 / 8, 48, 1);
    median3x3_kernel<<<grid, block>>>(in, out);
}